// round 1
// baseline (speedup 1.0000x reference)
#include <cuda_runtime.h>
#include <math.h>

#define K_CODES 1024
#define D 64
#define ROWP 68                 // padded smem row (floats): 272B, 16B-aligned, 2-way-max bank groups
#define SMEM_BYTES ((64 * ROWP + 128 * ROWP + 64) * 4 + 64 * 4)

__device__ unsigned int g_counts[K_CODES];
__device__ float g_esq[K_CODES];
__device__ double g_sumsq;

// packed dual-fp32 FMA (Blackwell f32x2 path; ptxas never emits this from C++)
__device__ __forceinline__ void fma2(unsigned long long& d_, unsigned long long a,
                                     unsigned long long b) {
    asm("fma.rn.f32x2 %0, %1, %2, %0;" : "+l"(d_) : "l"(a), "l"(b));
}

// ---------------------------------------------------------------------------
// Kernel 1: zero scratch, precompute ||e_k||^2
// ---------------------------------------------------------------------------
__global__ void vq_init(const float* __restrict__ cb) {
    int k = blockIdx.x * blockDim.x + threadIdx.x;
    if (k < K_CODES) {
        g_counts[k] = 0u;
        float s = 0.f;
#pragma unroll 8
        for (int d = 0; d < D; ++d) {
            float v = cb[k * D + d];
            s = fmaf(v, v, s);
        }
        g_esq[k] = s;
        if (k == 0) g_sumsq = 0.0;
    }
}

// ---------------------------------------------------------------------------
// Kernel 2: distances + argmin + gather + histogram + sum of squared diff
//   CTA: 64 tokens x (8 chunks of 128 codes). 256 threads as 16x16.
//   Thread micro-tile: 4 tokens x 8 codes, f32x2 accumulators paired over D.
// ---------------------------------------------------------------------------
__global__ __launch_bounds__(256, 1) void vq_main(const float* __restrict__ z,
                                                  const float* __restrict__ cb,
                                                  float* __restrict__ out, int N) {
    extern __shared__ float sm[];
    float* zs  = sm;                                // [64][ROWP]
    float* cs  = sm + 64 * ROWP;                    // [128][ROWP]
    float* zsq = sm + 64 * ROWP + 128 * ROWP;       // [64]
    int*   widx = (int*)(zsq + 64);                 // [64]

    const int tid = threadIdx.x;
    const int tx = tid & 15, ty = tid >> 4;
    const int tok0 = blockIdx.x * 64;

    // stage z tile (tokens x D), padded rows
    for (int i = tid; i < 64 * 16; i += 256) {
        int r = i >> 4, c = i & 15;
        *reinterpret_cast<float4*>(&zs[r * ROWP + c * 4]) =
            *reinterpret_cast<const float4*>(&z[(size_t)(tok0 + r) * D + c * 4]);
    }
    __syncthreads();
    if (tid < 64) {
        float s = 0.f;
        for (int d = 0; d < D; ++d) {
            float v = zs[tid * ROWP + d];
            s = fmaf(v, v, s);
        }
        zsq[tid] = s;
    }
    __syncthreads();

    float zq[4];
#pragma unroll
    for (int i = 0; i < 4; ++i) zq[i] = zsq[ty * 4 + i];

    float best[4];
    int bidx[4];
#pragma unroll
    for (int i = 0; i < 4; ++i) { best[i] = 3.4e38f; bidx[i] = 0; }

    for (int ch = 0; ch < 8; ++ch) {
        __syncthreads();  // guard cs reuse
        for (int i = tid; i < 128 * 16; i += 256) {
            int r = i >> 4, c = i & 15;
            *reinterpret_cast<float4*>(&cs[r * ROWP + c * 4]) =
                *reinterpret_cast<const float4*>(&cb[(size_t)(ch * 128 + r) * D + c * 4]);
        }
        __syncthreads();

        unsigned long long acc[4][8];
#pragma unroll
        for (int i = 0; i < 4; ++i)
#pragma unroll
            for (int j = 0; j < 8; ++j) acc[i][j] = 0ull;

#pragma unroll
        for (int d4 = 0; d4 < 16; ++d4) {
            ulonglong2 a[4], b[8];
#pragma unroll
            for (int i = 0; i < 4; ++i)
                a[i] = *reinterpret_cast<const ulonglong2*>(
                    &zs[(ty * 4 + i) * ROWP + d4 * 4]);
#pragma unroll
            for (int j = 0; j < 8; ++j)
                b[j] = *reinterpret_cast<const ulonglong2*>(
                    &cs[(tx + 16 * j) * ROWP + d4 * 4]);
#pragma unroll
            for (int i = 0; i < 4; ++i)
#pragma unroll
                for (int j = 0; j < 8; ++j) {
                    fma2(acc[i][j], a[i].x, b[j].x);  // even-d partials
                    fma2(acc[i][j], a[i].y, b[j].y);  // odd-d partials
                }
        }

        // scores: exact reference formula (z_sq - 2*dot) + e_sq in fp32.
        // j ascending => code index ascending => strict '<' keeps first min.
#pragma unroll
        for (int j = 0; j < 8; ++j) {
            int cg = ch * 128 + tx + 16 * j;
            float esq = g_esq[cg];
#pragma unroll
            for (int i = 0; i < 4; ++i) {
                float2 p = *reinterpret_cast<float2*>(&acc[i][j]);
                float dot = p.x + p.y;
                float s = (zq[i] - 2.0f * dot) + esq;
                if (s < best[i]) { best[i] = s; bidx[i] = cg; }
            }
        }
    }

    // cross-thread argmin reduce (overlay scratch on cs region)
    __syncthreads();
    float* rv = cs;                     // [64][16]
    int* ri = (int*)(cs + 64 * 16);     // [64][16]
#pragma unroll
    for (int i = 0; i < 4; ++i) {
        int t = ty * 4 + i;
        rv[t * 16 + tx] = best[i];
        ri[t * 16 + tx] = bidx[i];
    }
    __syncthreads();
    if (tid < 64) {
        float bv = rv[tid * 16];
        int bi = ri[tid * 16];
        for (int x = 1; x < 16; ++x) {
            float v = rv[tid * 16 + x];
            int ix = ri[tid * 16 + x];
            if (v < bv || (v == bv && ix < bi)) { bv = v; bi = ix; }
        }
        widx[tid] = bi;
        out[(size_t)N * D + tok0 + tid] = (float)bi;         // indices section
        atomicAdd(&g_counts[bi], 1u);
    }
    __syncthreads();

    // gather z_q, write output rows, accumulate sum((z_q - z_e)^2)
    int t = tid >> 2, seg = tid & 3;
    int bi = widx[t];
    float part = 0.f;
#pragma unroll
    for (int c4 = 0; c4 < 4; ++c4) {
        int d = seg * 16 + c4 * 4;
        float4 cv = *reinterpret_cast<const float4*>(&cb[(size_t)bi * D + d]);
        *reinterpret_cast<float4*>(&out[(size_t)(tok0 + t) * D + d]) = cv;
        float4 zv = *reinterpret_cast<const float4*>(&zs[t * ROWP + d]);
        float dx = cv.x - zv.x, dy = cv.y - zv.y;
        float dz = cv.z - zv.z, dw = cv.w - zv.w;
        part += dx * dx + dy * dy + dz * dz + dw * dw;
    }
#pragma unroll
    for (int off = 16; off > 0; off >>= 1)
        part += __shfl_down_sync(0xffffffffu, part, off);
    __shared__ float bsum;
    if (tid == 0) bsum = 0.f;
    __syncthreads();
    if ((tid & 31) == 0) atomicAdd(&bsum, part);
    __syncthreads();
    if (tid == 0) atomicAdd(&g_sumsq, (double)bsum);
}

// ---------------------------------------------------------------------------
// Kernel 3: entropy / perplexity / losses
// ---------------------------------------------------------------------------
__global__ void vq_finalize(float* __restrict__ out, int N) {
    __shared__ double red[1024];
    int k = threadIdx.x;
    float cnt = (float)g_counts[k];
    float avg = cnt / (float)N + 1e-10f;   // mimic fp32 avg_probs
    double p = (double)avg;
    red[k] = -p * log(p);
    __syncthreads();
    for (int s = 512; s > 0; s >>= 1) {
        if (k < s) red[k] += red[k + s];
        __syncthreads();
    }
    if (k == 0) {
        double H = red[0];
        double mean = g_sumsq / ((double)N * D);
        size_t base = (size_t)N * D + N;
        out[base + 0] = (float)mean;                           // codebook_loss
        out[base + 1] = (float)(0.25 * mean);                  // commitment_loss
        out[base + 2] = (float)(-0.1 * (H / log(1024.0)));     // entropy_loss
        out[base + 3] = (float)exp(H);                         // perplexity
    }
}

// ---------------------------------------------------------------------------
extern "C" void kernel_launch(void* const* d_in, const int* in_sizes, int n_in,
                              void* d_out, int out_size) {
    const float* z = (const float*)d_in[0];
    const float* cb = (const float*)d_in[1];
    float* out = (float*)d_out;
    int N = in_sizes[0] / D;

    cudaFuncSetAttribute(vq_main, cudaFuncAttributeMaxDynamicSharedMemorySize,
                         SMEM_BYTES);

    vq_init<<<(K_CODES + 255) / 256, 256>>>(cb);
    vq_main<<<N / 64, 256, SMEM_BYTES>>>(z, cb, out, N);
    vq_finalize<<<1, 1024>>>(out, N);
}